// round 10
// baseline (speedup 1.0000x reference)
#include <cuda_runtime.h>
#include <math.h>

// Problem constants
#define NYg    256
#define PMLc   20
#define PADc   22          // PML + FD_PAD
#define NP     300         // NYP == NXP
#define SXc    320         // padded row stride (floats)
#define Gc     4           // zero guard ring width
#define ARc    (NP + 2*Gc) // 308 rows allocated
#define Fc     (ARc*SXc)   // floats per field = 98560
#define NTc    250
#define NSHOTc 2
#define NSRCc  8
#define NRECc  64

#define DTc 0.0005f
#define Hc  5.0f

// Persistent-kernel config
#define NCTA 120
#define TPB  640            // two 320-thread row-groups per CTA
#define CPS  (NCTA/NSHOTc)  // 60 CTAs per shot
#define RPC  (NP/CPS)       // 5 rows per CTA
#define RN_MAX 3            // max owned rows per group (g0:3, g1:2)
#define PR_MAX (RN_MAX+4)   // max psiy rows per group (7)
#define CN_MAX (RN_MAX+8)   // max column rows per group (11)
#define WSROWS (RPC+8)      // 13 smem-staged wfc rows per CTA

// Per-shot fields: w0,w1,py0,py1 (psix in smem, zeta/wfm in regs). v2 -> field 8
__device__ float g_state[9*Fc];
__device__ float g_a[NP];
__device__ float g_b[NP];
// Mailboxes padded to 128B lines
__device__ unsigned g_arr[NCTA*32];
__device__ unsigned g_go[NCTA*32];

__device__ __forceinline__ int IDX(int y, int x) { return (y+Gc)*SXc + (x+Gc); }

__device__ __forceinline__ unsigned ld_acq(const unsigned* p) {
    unsigned v;
    asm volatile("ld.acquire.gpu.u32 %0, [%1];" : "=r"(v) : "l"(p));
    return v;
}
__device__ __forceinline__ void st_rel(unsigned* p, unsigned v) {
    asm volatile("st.release.gpu.u32 [%0], %1;" :: "l"(p), "r"(v) : "memory");
}

// Barrier over CTAs [leader, leader+n): distributed mailboxes, leader collects
// and releases. Phase equality is replay-safe (stale value = final phase can
// alias only the last barrier, after which no data is read).
__device__ __forceinline__ void gbar_dom(int cta, int leader, int n, unsigned ph) {
    __syncthreads();
    if (cta == leader) {
        int k = threadIdx.x;
        if (k >= 1 && k < n) {
            while (ld_acq(&g_arr[(leader+k)*32]) != ph) { }
        }
        __syncthreads();
        if (k >= 1 && k < n) {
            st_rel(&g_go[(leader+k)*32], ph);
        }
        __syncthreads();
    } else {
        if (threadIdx.x == 0) {
            st_rel(&g_arr[cta*32], ph);
            while (ld_acq(&g_go[cta*32]) != ph) { }
        }
        __syncthreads();
    }
}

extern "C" __global__ void __launch_bounds__(TPB, 1)
wave_kernel(const float* __restrict__ v,
            const float* __restrict__ amp,
            const void*  __restrict__ sloc,
            const void*  __restrict__ rloc,
            float* __restrict__ out)
{
    const int cta = blockIdx.x, tid = threadIdx.x;
    const int gt = cta*TPB + tid, GT = NCTA*TPB;

    // ---------------- init (every launch: deterministic) ----------------
    for (int i = gt; i < 8*Fc; i += GT) g_state[i] = 0.0f;

    for (int i = gt; i < NP; i += GT) {
        float fi = (float)i;
        float frac = fmaxf((float)PADc - fi, fi - (float)(NP - PADc - 1)) / (float)PMLc;
        frac = fminf(fmaxf(frac, 0.0f), 1.0f);
        float smax = 3.0f * 4000.0f * logf(1000.0f) / (2.0f * (float)PMLc * Hc);
        float sig  = smax * frac * frac;
        float alp  = 3.14159265358979f * 25.0f * (1.0f - frac);
        float bb   = expf(-(sig + alp) * DTc);
        g_b[i] = bb;
        g_a[i] = sig / (sig + alp + 1e-9f) * (bb - 1.0f);
    }

    for (int i = gt; i < NP*NP; i += GT) {
        int y = i / NP, x = i - y*NP;
        int vy = min(max(y - PADc, 0), NYg - 1);
        int vx = min(max(x - PADc, 0), NYg - 1);
        float vv = v[vy*NYg + vx];
        g_state[8*Fc + IDX(y,x)] = vv * vv * (DTc*DTc);
    }

    const int shot   = cta / CPS;
    const int leader = shot * CPS;
    const int y0     = (cta % CPS) * RPC;

    // Row-group split: g0 -> local rows 0..2, g1 -> local rows 3..4
    const int g   = (tid >= 320) ? 1 : 0;
    const int x   = tid - g*320;
    const int RLO = g ? 3 : 0;
    const int RN  = g ? 2 : 3;
    const int yb  = y0 + RLO;          // first owned row of this group
    const int PR  = RN + 4;            // psiy rows (yb-2 .. yb+RN+1)
    const int CN  = RN + 8;            // column rows (yb-4 .. yb+RN+3)

    __shared__ int   sh_key[NSRCc];
    __shared__ float sh_scale[NSRCc];
    __shared__ float ws[WSROWS][SXc];  // staged wfc rows y0-4..y0+8 (x-guards 0)
    __shared__ float psix_s[RPC][SXc]; // persistent psix (x-guards 0)
    __shared__ int   sh_rn;
    __shared__ int   sh_rr2[NRECc];
    __shared__ int   sh_rx[NRECc];
    __shared__ int   sh_ro[NRECc];

    for (int i = tid; i < RPC*SXc; i += TPB) ((float*)psix_s)[i] = 0.0f;
    for (int i = tid; i < WSROWS*SXc; i += TPB) ((float*)ws)[i] = 0.0f;  // guards

    if (tid < NSRCc) {
        const unsigned* w32 = (const unsigned*)sloc;
        bool is64 = true;
        for (int i = 1; i < NSHOTc*NSRCc*2; i += 2)
            if (w32[i] != 0u) { is64 = false; break; }
        int e = (shot*NSRCc + tid) * 2;
        int sy, sx;
        if (is64) { sy = (int)w32[2*e]; sx = (int)w32[2*(e+1)]; }
        else      { const int* w = (const int*)sloc; sy = w[e]; sx = w[e+1]; }
        float vv = v[sy*NYg + sx];
        sh_key[tid]   = ((sy + PADc) << 9) | (sx + PADc);
        sh_scale[tid] = vv * vv * (DTc*DTc);
    }
    if (tid == 0) {
        const unsigned* w32 = (const unsigned*)rloc;
        bool is64 = true;
        for (int i = 1; i < NSHOTc*NRECc*2; i += 2)
            if (w32[i] != 0u) { is64 = false; break; }
        int n = 0;
        for (int rr = 0; rr < NRECc; rr++) {
            int e = (shot*NRECc + rr) * 2;
            int ry, rx;
            if (is64) { ry = (int)w32[2*e]; rx = (int)w32[2*(e+1)]; }
            else      { const int* w = (const int*)rloc; ry = w[e]; rx = w[e+1]; }
            int yp = ry + PADc;
            if (yp >= y0 && yp < y0 + RPC) {
                sh_rr2[n] = yp - y0;
                sh_rx[n]  = rx + PADc;
                sh_ro[n]  = shot*NRECc + rr;
                n++;
            }
        }
        sh_rn = n;
    }

    unsigned ph = 0;
    gbar_dom(cta, 0, NCTA, ++ph);   // GLOBAL: init visible everywhere

    // ---------------- per-thread setup ----------------
    float* wbase  = g_state + shot*4*Fc;
    float* pybase = wbase + 2*Fc;
    const float* v2 = g_state + 8*Fc;
    const float* amp_s = amp + shot*NSRCc*NTc;

    const float iH  = 1.0f / Hc;
    const float iH2 = 1.0f / (Hc*Hc);
    const float C1A =  0.66666666666666666f, C1B = -0.08333333333333333f;
    const float C2A =  1.33333333333333333f, C2B = -0.08333333333333333f, C2C = -2.5f;

    const bool act = (x < NP);

    float ayr[PR_MAX], byr[PR_MAX];
    #pragma unroll
    for (int r = 0; r < PR_MAX; r++) {
        int y = yb - 2 + r;
        bool in = (r < PR) && (y >= 0 && y < NP);
        ayr[r] = in ? g_a[y] : 0.0f;
        byr[r] = in ? g_b[y] : 0.0f;
    }
    const float axv = act ? g_a[x] : 0.0f;
    const float bxv = act ? g_b[x] : 0.0f;

    bool srow[RN_MAX];
    #pragma unroll
    for (int r2 = 0; r2 < RN_MAX; r2++) {
        bool s = false;
        #pragma unroll
        for (int j = 0; j < NSRCc; j++) s = s || ((sh_key[j] >> 9) == (yb + r2));
        srow[r2] = (r2 < RN) && s;
    }
    const int nrec = sh_rn;

    float psr[RN_MAX], zyr[RN_MAX], zxr[RN_MAX], wold[RN_MAX];
    #pragma unroll
    for (int r2 = 0; r2 < RN_MAX; r2++) { psr[r2]=0.f; zyr[r2]=0.f; zxr[r2]=0.f; wold[r2]=0.f; }

    int cur = 0;

    // ---------------- time loop: ONE per-shot barrier per step ----------------
    for (int t = 0; t < NTc; t++) {
        const float* wfc = wbase + cur*Fc;
        float*       wst = wbase + (cur^1)*Fc;
        const int pb = t & 1;
        const float* pyold = pybase + (pb^1)*Fc;
        float*       pynew = pybase + pb*Fc;

        // Cooperative stage: wfc rows y0-4..y0+8 into smem (coalesced, ~7 LDG/thread)
        for (int i = tid; i < WSROWS*NP; i += TPB) {
            int r  = i / NP;
            int xx = i - r*NP;
            ws[r][xx+4] = __ldcg(wfc + IDX(y0 - 4 + r, xx));
        }
        // psiy halo loads (cross-CTA/group; psiy==0 where a==0 by induction)
        float poh[4];
        if (act) {
            poh[0] = (ayr[0]    != 0.0f) ? __ldcg(pyold + IDX(yb-2,    x)) : 0.0f;
            poh[1] = (ayr[1]    != 0.0f) ? __ldcg(pyold + IDX(yb-1,    x)) : 0.0f;
            poh[2] = (ayr[PR-2] != 0.0f) ? __ldcg(pyold + IDX(yb+RN,   x)) : 0.0f;
            poh[3] = (ayr[PR-1] != 0.0f) ? __ldcg(pyold + IDX(yb+RN+1, x)) : 0.0f;
        }
        __syncthreads();   // ws staged

        float s1[RN_MAX], s2[RN_MAX], cen[RN_MAX];
        float py[PR_MAX];

        if (act) {
            // Pull this group's column out of smem: c[k] = wfc(yb-4+k, x)
            float c[CN_MAX];
            #pragma unroll
            for (int k = 0; k < CN_MAX; k++)
                if (k < CN) c[k] = ws[RLO + k][x+4];

            // psiy update (owned + recomputed halo rows)
            #pragma unroll
            for (int r = 0; r < PR_MAX; r++) {
                if (r < PR) {
                    int y = yb - 2 + r;
                    float dwdy = (C1A*(c[r+3]-c[r+1]) + C1B*(c[r+4]-c[r])) * iH;
                    float po;
                    if (r == 0) po = poh[0];
                    else if (r == 1) po = poh[1];
                    else if (r == PR-2) po = poh[2];
                    else if (r == PR-1) po = poh[3];
                    else po = psr[r-2];
                    float pn = byr[r]*po + ayr[r]*dwdy;
                    if (y < 0 || y >= NP) pn = 0.0f;
                    py[r] = pn;
                }
            }
            #pragma unroll
            for (int r2 = 0; r2 < RN_MAX; r2++) {
                if (r2 < RN) {
                    psr[r2] = py[r2+2];
                    if (ayr[r2+2] != 0.0f)
                        pynew[IDX(yb + r2, x)] = py[r2+2];
                }
            }

            // Owned rows: derivatives + psix update (x-taps from smem)
            #pragma unroll
            for (int r2 = 0; r2 < RN_MAX; r2++) {
                if (r2 < RN) {
                    int m = r2 + 4;           // index into c[] (rel. to yb-4)
                    int sm = RLO + m;         // smem row (rel. to y0-4)
                    float b1 = ws[sm][x+3], b2 = ws[sm][x+5];
                    float b3 = ws[sm][x+2], b4 = ws[sm][x+6];
                    float d2y  = (C2C*c[m] + C2A*(c[m-1]+c[m+1]) + C2B*(c[m-2]+c[m+2])) * iH2;
                    float d2x  = (C2C*c[m] + C2A*(b1+b2)       + C2B*(b3+b4))         * iH2;
                    float dwdx = (C1A*(b2-b1) + C1B*(b4-b3)) * iH;
                    float dpy  = (C1A*(py[r2+3]-py[r2+1]) + C1B*(py[r2+4]-py[r2])) * iH;
                    float pxn  = bxv*psix_s[RLO+r2][x+4] + axv*dwdx;
                    psix_s[RLO+r2][x+4] = pxn;
                    s1[r2] = d2y + dpy;
                    s2[r2] = d2x;
                    cen[r2] = c[m];
                }
            }
        }
        __syncthreads();   // psix x-taps ready

        if (act) {
            #pragma unroll
            for (int r2 = 0; r2 < RN_MAX; r2++) {
                if (r2 < RN) {
                    int y = yb + r2;
                    int p = IDX(y, x);
                    float dpx = (C1A*(psix_s[RLO+r2][x+5]-psix_s[RLO+r2][x+3])
                               + C1B*(psix_s[RLO+r2][x+6]-psix_s[RLO+r2][x+2])) * iH;
                    float ayv = ayr[r2+2], byv = byr[r2+2];
                    float zyv = byv*zyr[r2] + ayv*s1[r2];             zyr[r2] = zyv;
                    float zxv = bxv*zxr[r2] + axv*(s2[r2] + dpx);     zxr[r2] = zxv;
                    float lap = s1[r2] + s2[r2] + dpx + zyv + zxv;
                    float wnew = 2.0f*cen[r2] - wold[r2] + v2[p]*lap;
                    if (srow[r2]) {
                        int key = (y << 9) | x;
                        #pragma unroll
                        for (int j = 0; j < NSRCc; j++)
                            if (sh_key[j] == key) wnew += sh_scale[j] * amp_s[j*NTc + t];
                    }
                    wold[r2] = cen[r2];
                    wst[p] = wnew;
                    for (int j = 0; j < nrec; j++)
                        if (sh_rr2[j] == RLO + r2 && sh_rx[j] == x)
                            out[sh_ro[j]*NTc + t] = wnew;
                }
            }
        }

        gbar_dom(cta, leader, CPS, ++ph);   // per-shot: 60-CTA barrier
        cur ^= 1;
    }
}

extern "C" void kernel_launch(void* const* d_in, const int* in_sizes, int n_in,
                              void* d_out, int out_size)
{
    const float* v    = (const float*)d_in[0];
    const float* amp  = (const float*)d_in[1];
    const void*  sloc = d_in[2];
    const void*  rloc = d_in[3];
    wave_kernel<<<NCTA, TPB>>>(v, amp, sloc, rloc, (float*)d_out);
}

// round 11
// speedup vs baseline: 1.4626x; 1.4626x over previous
#include <cuda_runtime.h>
#include <math.h>

// Problem constants
#define NYg    256
#define PMLc   20
#define PADc   22          // PML + FD_PAD
#define NP     300         // NYP == NXP
#define SXc    320         // padded row stride (floats)
#define Gc     4           // zero guard ring width
#define ARc    (NP + 2*Gc) // 308 rows allocated
#define Fc     (ARc*SXc)   // floats per field = 98560
#define NTc    250
#define NSHOTc 2
#define NSRCc  8
#define NRECc  64

#define DTc 0.0005f
#define Hc  5.0f

// Persistent-kernel config
#define NCCTA 120           // compute CTAs
#define NCTA  122           // + 2 dedicated barrier-leader CTAs (one per shot)
#define TPB   640           // two 320-thread row-groups per compute CTA
#define CPS   (NCCTA/NSHOTc) // 60 compute CTAs per shot
#define RPC   (NP/CPS)      // 5 rows per CTA
#define RN_MAX 3            // max owned rows per group (g0:3, g1:2)
#define PR_MAX (RN_MAX+4)   // max psiy rows per group (7)
#define CN_MAX (RN_MAX+8)   // max column rows per group (11)

// Per-shot fields: w0,w1,py0,py1 (psix in smem, zeta/wfm in regs). v2 -> field 8
__device__ float g_state[9*Fc];
__device__ float g_a[NP];
__device__ float g_b[NP];
// Mailboxes padded to 128B lines
__device__ unsigned g_arr[NCTA*32];
__device__ unsigned g_go[NCTA*32];

__device__ __forceinline__ int IDX(int y, int x) { return (y+Gc)*SXc + (x+Gc); }

__device__ __forceinline__ unsigned ld_acq(const unsigned* p) {
    unsigned v;
    asm volatile("ld.acquire.gpu.u32 %0, [%1];" : "=r"(v) : "l"(p));
    return v;
}
__device__ __forceinline__ void st_rel(unsigned* p, unsigned v) {
    asm volatile("st.release.gpu.u32 [%0], %1;" :: "l"(p), "r"(v) : "memory");
}

// One-time global init barrier (122 CTAs, leader = CTA 0). Release value 1 is
// also written to slot 0 so CTA 0's first step-wait (go==1) passes.
// Replay safety: stale g_arr from a prior launch is 251 (compute) or 1
// (leader CTAs 120/121). Leader slots' stale go==1 only lets the leader CTAs
// start their poll loops early, which is harmless (they spin until this
// launch's arrivals appear; arrivals are gated by the go chain).
__device__ __forceinline__ void init_bar(int cta) {
    __syncthreads();
    if (cta == 0) {
        if (threadIdx.x >= 1 && threadIdx.x < NCTA) {
            while (ld_acq(&g_arr[threadIdx.x*32]) != 1u) { }
        }
        __syncthreads();
        if (threadIdx.x < NCTA) st_rel(&g_go[threadIdx.x*32], 1u);
        __syncthreads();
    } else {
        if (threadIdx.x == 0) {
            st_rel(&g_arr[cta*32], 1u);
            while (ld_acq(&g_go[cta*32]) != 1u) { }
        }
        __syncthreads();
    }
}

extern "C" __global__ void __launch_bounds__(TPB, 1)
wave_kernel(const float* __restrict__ v,
            const float* __restrict__ amp,
            const void*  __restrict__ sloc,
            const void*  __restrict__ rloc,
            float* __restrict__ out)
{
    const int cta = blockIdx.x, tid = threadIdx.x;
    const int gt = cta*TPB + tid, GT = NCTA*TPB;

    // ---------------- init (every launch: deterministic) ----------------
    for (int i = gt; i < 8*Fc; i += GT) g_state[i] = 0.0f;

    for (int i = gt; i < NP; i += GT) {
        float fi = (float)i;
        float frac = fmaxf((float)PADc - fi, fi - (float)(NP - PADc - 1)) / (float)PMLc;
        frac = fminf(fmaxf(frac, 0.0f), 1.0f);
        float smax = 3.0f * 4000.0f * logf(1000.0f) / (2.0f * (float)PMLc * Hc);
        float sig  = smax * frac * frac;
        float alp  = 3.14159265358979f * 25.0f * (1.0f - frac);
        float bb   = expf(-(sig + alp) * DTc);
        g_b[i] = bb;
        g_a[i] = sig / (sig + alp + 1e-9f) * (bb - 1.0f);
    }

    for (int i = gt; i < NP*NP; i += GT) {
        int y = i / NP, x = i - y*NP;
        int vy = min(max(y - PADc, 0), NYg - 1);
        int vx = min(max(x - PADc, 0), NYg - 1);
        float vv = v[vy*NYg + vx];
        g_state[8*Fc + IDX(y,x)] = vv * vv * (DTc*DTc);
    }

    const bool is_leader = (cta >= NCCTA);
    const int shot = is_leader ? (cta - NCCTA) : (cta / CPS);
    const int y0   = is_leader ? 0 : (cta % CPS) * RPC;

    // Row-group split: g0 -> local rows 0..2, g1 -> local rows 3..4
    const int g     = (tid >= 320) ? 1 : 0;
    const int x     = tid - g*320;
    const int RLO   = g ? 3 : 0;
    const int RN    = g ? 2 : 3;
    const int yb    = y0 + RLO;         // first owned row of this group
    const int PR    = RN + 4;           // psiy rows (yb-2 .. yb+RN+1)
    const int CN    = RN + 8;           // column rows (yb-4 .. yb+RN+3)
    const int OWNLO = 4 - RLO;          // c-index of first own-CTA row

    __shared__ int   sh_key[NSRCc];
    __shared__ float sh_scale[NSRCc];
    __shared__ float psix_s[RPC][SXc];  // persistent psix (x-guards 0)
    __shared__ int   sh_rn;
    __shared__ int   sh_rr2[NRECc];
    __shared__ int   sh_rx[NRECc];
    __shared__ int   sh_ro[NRECc];

    for (int i = tid; i < RPC*SXc; i += TPB) ((float*)psix_s)[i] = 0.0f;

    if (!is_leader && tid < NSRCc) {
        const unsigned* w32 = (const unsigned*)sloc;
        bool is64 = true;
        for (int i = 1; i < NSHOTc*NSRCc*2; i += 2)
            if (w32[i] != 0u) { is64 = false; break; }
        int e = (shot*NSRCc + tid) * 2;
        int sy, sx;
        if (is64) { sy = (int)w32[2*e]; sx = (int)w32[2*(e+1)]; }
        else      { const int* w = (const int*)sloc; sy = w[e]; sx = w[e+1]; }
        float vv = v[sy*NYg + sx];
        sh_key[tid]   = ((sy + PADc) << 9) | (sx + PADc);
        sh_scale[tid] = vv * vv * (DTc*DTc);
    }
    if (!is_leader && tid == 0) {
        const unsigned* w32 = (const unsigned*)rloc;
        bool is64 = true;
        for (int i = 1; i < NSHOTc*NRECc*2; i += 2)
            if (w32[i] != 0u) { is64 = false; break; }
        int n = 0;
        for (int rr = 0; rr < NRECc; rr++) {
            int e = (shot*NRECc + rr) * 2;
            int ry, rx;
            if (is64) { ry = (int)w32[2*e]; rx = (int)w32[2*(e+1)]; }
            else      { const int* w = (const int*)rloc; ry = w[e]; rx = w[e+1]; }
            int yp = ry + PADc;
            if (yp >= y0 && yp < y0 + RPC) {
                sh_rr2[n] = yp - y0;
                sh_rx[n]  = rx + PADc;
                sh_ro[n]  = shot*NRECc + rr;
                n++;
            }
        }
        sh_rn = n;
    }

    init_bar(cta);   // init visible everywhere

    // ---------------- dedicated barrier leaders (no compute) ----------------
    if (is_leader) {
        const int base = shot * CPS;
        for (unsigned val = 2; val <= (unsigned)(NTc + 1); val++) {
            if (tid < CPS) {
                while (ld_acq(&g_arr[(base + tid)*32]) != val) { }
            }
            __syncthreads();            // all 60 arrivals observed
            if (tid < CPS) {
                st_rel(&g_go[(base + tid)*32], val);
            }
            __syncthreads();
        }
        return;
    }

    // ---------------- compute CTA setup ----------------
    float* wbase  = g_state + shot*4*Fc;
    float* pybase = wbase + 2*Fc;
    const float* v2 = g_state + 8*Fc;
    const float* amp_s = amp + shot*NSRCc*NTc;

    const float iH  = 1.0f / Hc;
    const float iH2 = 1.0f / (Hc*Hc);
    const float C1A =  0.66666666666666666f, C1B = -0.08333333333333333f;
    const float C2A =  1.33333333333333333f, C2B = -0.08333333333333333f, C2C = -2.5f;

    const bool act = (x < NP);

    float ayr[PR_MAX], byr[PR_MAX];
    #pragma unroll
    for (int r = 0; r < PR_MAX; r++) {
        int y = yb - 2 + r;
        bool in = (r < PR) && (y >= 0 && y < NP);
        ayr[r] = in ? g_a[y] : 0.0f;
        byr[r] = in ? g_b[y] : 0.0f;
    }
    const float axv = act ? g_a[x] : 0.0f;
    const float bxv = act ? g_b[x] : 0.0f;

    // v2 is time-invariant: hoist into registers (valid after init barrier)
    float v2r[RN_MAX];
    #pragma unroll
    for (int r2 = 0; r2 < RN_MAX; r2++)
        v2r[r2] = (act && r2 < RN) ? v2[IDX(yb + r2, x)] : 0.0f;

    bool srow[RN_MAX];
    #pragma unroll
    for (int r2 = 0; r2 < RN_MAX; r2++) {
        bool s = false;
        #pragma unroll
        for (int j = 0; j < NSRCc; j++) s = s || ((sh_key[j] >> 9) == (yb + r2));
        srow[r2] = (r2 < RN) && s;
    }
    const int nrec = sh_rn;

    float psr[RN_MAX], zyr[RN_MAX], zxr[RN_MAX], wold[RN_MAX];
    #pragma unroll
    for (int r2 = 0; r2 < RN_MAX; r2++) { psr[r2]=0.f; zyr[r2]=0.f; zxr[r2]=0.f; wold[r2]=0.f; }

    int cur = 0;
    unsigned* my_arr = &g_arr[cta*32];
    unsigned* my_go  = &g_go[cta*32];

    // ------------- time loop: split-phase barrier -------------
    // End of step t posts arr=t+2. Before y-path of step t we need go==t+1
    // (all shot CTAs done with step t-1). The x-path (phase A) depends only on
    // this CTA's own wfc rows (written by itself last step; intra-CTA L1
    // coherent after __syncthreads) -> runs BEFORE the wait, hiding the
    // leader's detect/release chain.
    for (int t = 0; t < NTc; t++) {
        const float* wfc = wbase + cur*Fc;
        float*       wst = wbase + (cur^1)*Fc;
        const int pb = t & 1;
        const float* pyold = pybase + (pb^1)*Fc;
        float*       pynew = pybase + pb*Fc;

        float c[CN_MAX], d2xs[RN_MAX], sxa[RN_MAX];

        // ---- Phase A part 1: own-row x-derivatives + psix update (plain/L1) ----
        if (act) {
            #pragma unroll
            for (int r2 = 0; r2 < RN_MAX; r2++) {
                if (r2 < RN) {
                    int p = IDX(yb + r2, x);
                    float b3 = wfc[p-2], b1 = wfc[p-1], ct = wfc[p];
                    float b2 = wfc[p+1], b4 = wfc[p+2];
                    c[r2+4] = ct;
                    float d2x  = (C2C*ct + C2A*(b1+b2) + C2B*(b3+b4)) * iH2;
                    float dwdx = (C1A*(b2-b1) + C1B*(b4-b3)) * iH;
                    float pxn  = bxv*psix_s[RLO+r2][x+4] + axv*dwdx;
                    psix_s[RLO+r2][x+4] = pxn;
                    d2xs[r2] = d2x;
                }
            }
            // remaining own-CTA rows of this thread's column (other group's rows)
            #pragma unroll
            for (int k = 0; k < CN_MAX; k++) {
                if (k < CN) {
                    bool own = (k >= OWNLO) && (k < OWNLO + 5);
                    bool grp = (k >= 4) && (k < 4 + RN);
                    if (own && !grp) c[k] = wfc[IDX(yb - 4 + k, x)];
                }
            }
        }
        __syncthreads();   // psix taps ready

        // ---- Phase A part 2: dpx, zetax (still own data only) ----
        if (act) {
            #pragma unroll
            for (int r2 = 0; r2 < RN_MAX; r2++) {
                if (r2 < RN) {
                    float dpx = (C1A*(psix_s[RLO+r2][x+5]-psix_s[RLO+r2][x+3])
                               + C1B*(psix_s[RLO+r2][x+6]-psix_s[RLO+r2][x+2])) * iH;
                    float zxv = bxv*zxr[r2] + axv*(d2xs[r2] + dpx);
                    zxr[r2] = zxv;
                    sxa[r2] = d2xs[r2] + dpx + zxv;
                }
            }
        }

        // ---- Wait for shot-wide completion of step t-1 ----
        if (tid == 0) {
            while (ld_acq(my_go) != (unsigned)(t + 1)) { }
        }
        __syncthreads();

        // ---- Phase B: halo loads + y-path + combine + stores ----
        if (act) {
            // halo rows of the column (neighbor CTA data, L2)
            #pragma unroll
            for (int k = 0; k < CN_MAX; k++) {
                if (k < CN) {
                    bool own = (k >= OWNLO) && (k < OWNLO + 5);
                    if (!own) c[k] = __ldcg(wfc + IDX(yb - 4 + k, x));
                }
            }
            // psiy halo (psiy == 0 where a == 0, by induction from zero init)
            float poh[4];
            poh[0] = (ayr[0]    != 0.0f) ? __ldcg(pyold + IDX(yb-2,    x)) : 0.0f;
            poh[1] = (ayr[1]    != 0.0f) ? __ldcg(pyold + IDX(yb-1,    x)) : 0.0f;
            poh[2] = (ayr[PR-2] != 0.0f) ? __ldcg(pyold + IDX(yb+RN,   x)) : 0.0f;
            poh[3] = (ayr[PR-1] != 0.0f) ? __ldcg(pyold + IDX(yb+RN+1, x)) : 0.0f;

            // psiy update (owned + recomputed halo rows)
            float py[PR_MAX];
            #pragma unroll
            for (int r = 0; r < PR_MAX; r++) {
                if (r < PR) {
                    int y = yb - 2 + r;
                    float dwdy = (C1A*(c[r+3]-c[r+1]) + C1B*(c[r+4]-c[r])) * iH;
                    float po;
                    if (r == 0) po = poh[0];
                    else if (r == 1) po = poh[1];
                    else if (r == PR-2) po = poh[2];
                    else if (r == PR-1) po = poh[3];
                    else po = psr[r-2];
                    float pn = byr[r]*po + ayr[r]*dwdy;
                    if (y < 0 || y >= NP) pn = 0.0f;
                    py[r] = pn;
                }
            }
            #pragma unroll
            for (int r2 = 0; r2 < RN_MAX; r2++) {
                if (r2 < RN) {
                    psr[r2] = py[r2+2];
                    if (ayr[r2+2] != 0.0f)
                        pynew[IDX(yb + r2, x)] = py[r2+2];
                }
            }

            #pragma unroll
            for (int r2 = 0; r2 < RN_MAX; r2++) {
                if (r2 < RN) {
                    int m = r2 + 4;
                    int y = yb + r2;
                    float d2y = (C2C*c[m] + C2A*(c[m-1]+c[m+1]) + C2B*(c[m-2]+c[m+2])) * iH2;
                    float dpy = (C1A*(py[r2+3]-py[r2+1]) + C1B*(py[r2+4]-py[r2])) * iH;
                    float s1  = d2y + dpy;
                    float zyv = byr[r2+2]*zyr[r2] + ayr[r2+2]*s1;
                    zyr[r2] = zyv;
                    float lap = s1 + zyv + sxa[r2];
                    float wnew = 2.0f*c[m] - wold[r2] + v2r[r2]*lap;
                    if (srow[r2]) {
                        int key = (y << 9) | x;
                        #pragma unroll
                        for (int j = 0; j < NSRCc; j++)
                            if (sh_key[j] == key) wnew += sh_scale[j] * amp_s[j*NTc + t];
                    }
                    wold[r2] = c[m];
                    wst[IDX(y, x)] = wnew;
                    for (int j = 0; j < nrec; j++)
                        if (sh_rr2[j] == RLO + r2 && sh_rx[j] == x)
                            out[sh_ro[j]*NTc + t] = wnew;
                }
            }
        }
        __syncthreads();   // all stores issued

        // ---- Post arrival: this CTA completed step t ----
        if (tid == 0) {
            st_rel(my_arr, (unsigned)(t + 2));
        }
        cur ^= 1;
    }
}

extern "C" void kernel_launch(void* const* d_in, const int* in_sizes, int n_in,
                              void* d_out, int out_size)
{
    const float* v    = (const float*)d_in[0];
    const float* amp  = (const float*)d_in[1];
    const void*  sloc = d_in[2];
    const void*  rloc = d_in[3];
    wave_kernel<<<NCTA, TPB>>>(v, amp, sloc, rloc, (float*)d_out);
}

// round 12
// speedup vs baseline: 1.5391x; 1.0523x over previous
#include <cuda_runtime.h>
#include <math.h>

// Problem constants
#define NYg    256
#define PMLc   20
#define PADc   22          // PML + FD_PAD
#define NP     300         // NYP == NXP
#define SXc    320         // padded row stride (floats)
#define Gc     4           // zero guard ring width
#define ARc    (NP + 2*Gc) // 308 rows allocated
#define Fc     (ARc*SXc)   // floats per field = 98560
#define NTc    250
#define NSHOTc 2
#define NSRCc  8
#define NRECc  64

#define DTc 0.0005f
#define Hc  5.0f

// Persistent-kernel config
#define NCTA  120           // compute CTAs only (no leaders)
#define TPB   640           // two 320-thread row-groups per CTA
#define CPS   (NCTA/NSHOTc) // 60 CTAs per shot
#define RPC   (NP/CPS)      // 5 rows per CTA
#define RN_MAX 3            // max owned rows per group (g0:3, g1:2)
#define PR_MAX (RN_MAX+4)   // max psiy rows per group (7)
#define CN_MAX (RN_MAX+8)   // max column rows per group (11)

// Per-shot fields: w0,w1,py0,py1 (psix in smem, zeta/wfm in regs). v2 -> field 8
__device__ float g_state[9*Fc];
__device__ float g_a[NP];
__device__ float g_b[NP];
// Mailboxes padded to 128B lines
__device__ unsigned g_arr[NCTA*32];   // arrival/progress counters
__device__ unsigned g_go[NCTA*32];    // init-barrier release only

__device__ __forceinline__ int IDX(int y, int x) { return (y+Gc)*SXc + (x+Gc); }

__device__ __forceinline__ unsigned ld_acq(const unsigned* p) {
    unsigned v;
    asm volatile("ld.acquire.gpu.u32 %0, [%1];" : "=r"(v) : "l"(p));
    return v;
}
__device__ __forceinline__ void st_rel(unsigned* p, unsigned v) {
    asm volatile("st.release.gpu.u32 [%0], %1;" :: "l"(p), "r"(v) : "memory");
}
__device__ __forceinline__ void st_rlx(unsigned* p, unsigned v) {
    asm volatile("st.relaxed.gpu.u32 [%0], %1;" :: "l"(p), "r"(v) : "memory");
}

// One-time global init barrier. Replay-safe: each CTA zeroes its OWN go slot
// before its release-arrival, so a stale go==1 from a prior launch cannot leak
// a waiter through (owner's go=0 happens-before CTA0's go=1 via the arr
// release/acquire chain; coherence makes 1 the final value). After this
// barrier every g_arr slot is exactly 1, so subsequent monotone >= waits only
// observe this launch's values.
__device__ __forceinline__ void init_bar(int cta) {
    __syncthreads();
    if (cta == 0) {
        if (threadIdx.x >= 1 && threadIdx.x < NCTA) {
            while (ld_acq(&g_arr[threadIdx.x*32]) != 1u) { }
        }
        __syncthreads();
        if (threadIdx.x >= 1 && threadIdx.x < NCTA) st_rel(&g_go[threadIdx.x*32], 1u);
        if (threadIdx.x == 0) st_rel(&g_arr[0], 1u);
        __syncthreads();
    } else {
        if (threadIdx.x == 0) {
            st_rlx(&g_go[cta*32], 0u);       // kill stale release value
            st_rel(&g_arr[cta*32], 1u);
            while (ld_acq(&g_go[cta*32]) != 1u) { }
        }
        __syncthreads();
    }
}

extern "C" __global__ void __launch_bounds__(TPB, 1)
wave_kernel(const float* __restrict__ v,
            const float* __restrict__ amp,
            const void*  __restrict__ sloc,
            const void*  __restrict__ rloc,
            float* __restrict__ out)
{
    const int cta = blockIdx.x, tid = threadIdx.x;
    const int gt = cta*TPB + tid, GT = NCTA*TPB;

    // ---------------- init (every launch: deterministic) ----------------
    for (int i = gt; i < 8*Fc; i += GT) g_state[i] = 0.0f;

    for (int i = gt; i < NP; i += GT) {
        float fi = (float)i;
        float frac = fmaxf((float)PADc - fi, fi - (float)(NP - PADc - 1)) / (float)PMLc;
        frac = fminf(fmaxf(frac, 0.0f), 1.0f);
        float smax = 3.0f * 4000.0f * logf(1000.0f) / (2.0f * (float)PMLc * Hc);
        float sig  = smax * frac * frac;
        float alp  = 3.14159265358979f * 25.0f * (1.0f - frac);
        float bb   = expf(-(sig + alp) * DTc);
        g_b[i] = bb;
        g_a[i] = sig / (sig + alp + 1e-9f) * (bb - 1.0f);
    }

    for (int i = gt; i < NP*NP; i += GT) {
        int y = i / NP, x = i - y*NP;
        int vy = min(max(y - PADc, 0), NYg - 1);
        int vx = min(max(x - PADc, 0), NYg - 1);
        float vv = v[vy*NYg + vx];
        g_state[8*Fc + IDX(y,x)] = vv * vv * (DTc*DTc);
    }

    const int shot = cta / CPS;
    const int pos  = cta % CPS;
    const int y0   = pos * RPC;
    const bool has_up = (pos > 0);
    const bool has_dn = (pos < CPS - 1);

    // Row-group split: g0 -> local rows 0..2, g1 -> local rows 3..4
    const int g     = (tid >= 320) ? 1 : 0;
    const int x     = tid - g*320;
    const int RLO   = g ? 3 : 0;
    const int RN    = g ? 2 : 3;
    const int yb    = y0 + RLO;         // first owned row of this group
    const int PR    = RN + 4;           // psiy rows (yb-2 .. yb+RN+1)
    const int CN    = RN + 8;           // column rows (yb-4 .. yb+RN+3)
    const int OWNLO = 4 - RLO;          // c-index of first own-CTA row

    __shared__ int   sh_key[NSRCc];
    __shared__ float sh_scale[NSRCc];
    __shared__ float psix_s[RPC][SXc];  // persistent psix (x-guards 0)
    __shared__ int   sh_rn;
    __shared__ int   sh_rr2[NRECc];
    __shared__ int   sh_rx[NRECc];
    __shared__ int   sh_ro[NRECc];

    for (int i = tid; i < RPC*SXc; i += TPB) ((float*)psix_s)[i] = 0.0f;

    if (tid < NSRCc) {
        const unsigned* w32 = (const unsigned*)sloc;
        bool is64 = true;
        for (int i = 1; i < NSHOTc*NSRCc*2; i += 2)
            if (w32[i] != 0u) { is64 = false; break; }
        int e = (shot*NSRCc + tid) * 2;
        int sy, sx;
        if (is64) { sy = (int)w32[2*e]; sx = (int)w32[2*(e+1)]; }
        else      { const int* w = (const int*)sloc; sy = w[e]; sx = w[e+1]; }
        float vv = v[sy*NYg + sx];
        sh_key[tid]   = ((sy + PADc) << 9) | (sx + PADc);
        sh_scale[tid] = vv * vv * (DTc*DTc);
    }
    if (tid == 0) {
        const unsigned* w32 = (const unsigned*)rloc;
        bool is64 = true;
        for (int i = 1; i < NSHOTc*NRECc*2; i += 2)
            if (w32[i] != 0u) { is64 = false; break; }
        int n = 0;
        for (int rr = 0; rr < NRECc; rr++) {
            int e = (shot*NRECc + rr) * 2;
            int ry, rx;
            if (is64) { ry = (int)w32[2*e]; rx = (int)w32[2*(e+1)]; }
            else      { const int* w = (const int*)rloc; ry = w[e]; rx = w[e+1]; }
            int yp = ry + PADc;
            if (yp >= y0 && yp < y0 + RPC) {
                sh_rr2[n] = yp - y0;
                sh_rx[n]  = rx + PADc;
                sh_ro[n]  = shot*NRECc + rr;
                n++;
            }
        }
        sh_rn = n;
    }

    init_bar(cta);   // init visible everywhere; all g_arr slots == 1

    // ---------------- compute CTA setup ----------------
    float* wbase  = g_state + shot*4*Fc;
    float* pybase = wbase + 2*Fc;
    const float* v2 = g_state + 8*Fc;
    const float* amp_s = amp + shot*NSRCc*NTc;

    const float iH  = 1.0f / Hc;
    const float iH2 = 1.0f / (Hc*Hc);
    const float C1A =  0.66666666666666666f, C1B = -0.08333333333333333f;
    const float C2A =  1.33333333333333333f, C2B = -0.08333333333333333f, C2C = -2.5f;

    const bool act = (x < NP);

    float ayr[PR_MAX], byr[PR_MAX];
    #pragma unroll
    for (int r = 0; r < PR_MAX; r++) {
        int y = yb - 2 + r;
        bool in = (r < PR) && (y >= 0 && y < NP);
        ayr[r] = in ? g_a[y] : 0.0f;
        byr[r] = in ? g_b[y] : 0.0f;
    }
    const float axv = act ? g_a[x] : 0.0f;
    const float bxv = act ? g_b[x] : 0.0f;

    // v2 is time-invariant: hoist into registers (valid after init barrier)
    float v2r[RN_MAX];
    #pragma unroll
    for (int r2 = 0; r2 < RN_MAX; r2++)
        v2r[r2] = (act && r2 < RN) ? v2[IDX(yb + r2, x)] : 0.0f;

    bool srow[RN_MAX];
    #pragma unroll
    for (int r2 = 0; r2 < RN_MAX; r2++) {
        bool s = false;
        #pragma unroll
        for (int j = 0; j < NSRCc; j++) s = s || ((sh_key[j] >> 9) == (yb + r2));
        srow[r2] = (r2 < RN) && s;
    }
    const int nrec = sh_rn;

    float psr[RN_MAX], zyr[RN_MAX], zxr[RN_MAX], wold[RN_MAX];
    #pragma unroll
    for (int r2 = 0; r2 < RN_MAX; r2++) { psr[r2]=0.f; zyr[r2]=0.f; zxr[r2]=0.f; wold[r2]=0.f; }

    int cur = 0;
    unsigned* my_arr = &g_arr[cta*32];
    const unsigned* up_arr = has_up ? &g_arr[(cta-1)*32] : my_arr;
    const unsigned* dn_arr = has_dn ? &g_arr[(cta+1)*32] : my_arr;

    // ------------- time loop: split-phase + neighbor-only sync -------------
    // arr[i] semantics: 1 after init; t+2 after completing step t.
    // Before Phase B of step t, wait arr[up/dn] >= t+1 (neighbor completed
    // step t-1). This guarantees (a) neighbor's step t-1 halo data is
    // released/visible, and (b) neighbor finished READING the double-buffer
    // halves my Phase-B stores overwrite. Symmetrically, my arrival (t+2,
    // posted after my reads+writes of step t) prevents neighbors' step t+1
    // writes from clobbering what I read at step t. All my global writes
    // occur in Phase B, after the wait; Phase A touches only regs + smem.
    for (int t = 0; t < NTc; t++) {
        const float* wfc = wbase + cur*Fc;
        float*       wst = wbase + (cur^1)*Fc;
        const int pb = t & 1;
        const float* pyold = pybase + (pb^1)*Fc;
        float*       pynew = pybase + pb*Fc;

        float c[CN_MAX], d2xs[RN_MAX], sxa[RN_MAX];

        // ---- Phase A part 1: own-row x-derivatives + psix update (plain/L1) ----
        if (act) {
            #pragma unroll
            for (int r2 = 0; r2 < RN_MAX; r2++) {
                if (r2 < RN) {
                    int p = IDX(yb + r2, x);
                    float b3 = wfc[p-2], b1 = wfc[p-1], ct = wfc[p];
                    float b2 = wfc[p+1], b4 = wfc[p+2];
                    c[r2+4] = ct;
                    float d2x  = (C2C*ct + C2A*(b1+b2) + C2B*(b3+b4)) * iH2;
                    float dwdx = (C1A*(b2-b1) + C1B*(b4-b3)) * iH;
                    float pxn  = bxv*psix_s[RLO+r2][x+4] + axv*dwdx;
                    psix_s[RLO+r2][x+4] = pxn;
                    d2xs[r2] = d2x;
                }
            }
            // remaining own-CTA rows of this thread's column (other group's rows)
            #pragma unroll
            for (int k = 0; k < CN_MAX; k++) {
                if (k < CN) {
                    bool own = (k >= OWNLO) && (k < OWNLO + 5);
                    bool grp = (k >= 4) && (k < 4 + RN);
                    if (own && !grp) c[k] = wfc[IDX(yb - 4 + k, x)];
                }
            }
        }
        __syncthreads();   // psix taps ready

        // ---- Phase A part 2: dpx, zetax (still own data only) ----
        if (act) {
            #pragma unroll
            for (int r2 = 0; r2 < RN_MAX; r2++) {
                if (r2 < RN) {
                    float dpx = (C1A*(psix_s[RLO+r2][x+5]-psix_s[RLO+r2][x+3])
                               + C1B*(psix_s[RLO+r2][x+6]-psix_s[RLO+r2][x+2])) * iH;
                    float zxv = bxv*zxr[r2] + axv*(d2xs[r2] + dpx);
                    zxr[r2] = zxv;
                    sxa[r2] = d2xs[r2] + dpx + zxv;
                }
            }
        }

        // ---- Neighbor-only wait: up/dn completed step t-1 ----
        {
            unsigned need = (unsigned)(t + 1);
            if (tid == 0  && has_up) { while (ld_acq(up_arr) < need) { } }
            if (tid == 32 && has_dn) { while (ld_acq(dn_arr) < need) { } }
        }
        __syncthreads();

        // ---- Phase B: halo loads + y-path + combine + stores ----
        if (act) {
            // halo rows of the column (neighbor CTA data, L2)
            #pragma unroll
            for (int k = 0; k < CN_MAX; k++) {
                if (k < CN) {
                    bool own = (k >= OWNLO) && (k < OWNLO + 5);
                    if (!own) c[k] = __ldcg(wfc + IDX(yb - 4 + k, x));
                }
            }
            // psiy halo (psiy == 0 where a == 0, by induction from zero init)
            float poh[4];
            poh[0] = (ayr[0]    != 0.0f) ? __ldcg(pyold + IDX(yb-2,    x)) : 0.0f;
            poh[1] = (ayr[1]    != 0.0f) ? __ldcg(pyold + IDX(yb-1,    x)) : 0.0f;
            poh[2] = (ayr[PR-2] != 0.0f) ? __ldcg(pyold + IDX(yb+RN,   x)) : 0.0f;
            poh[3] = (ayr[PR-1] != 0.0f) ? __ldcg(pyold + IDX(yb+RN+1, x)) : 0.0f;

            // psiy update (owned + recomputed halo rows)
            float py[PR_MAX];
            #pragma unroll
            for (int r = 0; r < PR_MAX; r++) {
                if (r < PR) {
                    int y = yb - 2 + r;
                    float dwdy = (C1A*(c[r+3]-c[r+1]) + C1B*(c[r+4]-c[r])) * iH;
                    float po;
                    if (r == 0) po = poh[0];
                    else if (r == 1) po = poh[1];
                    else if (r == PR-2) po = poh[2];
                    else if (r == PR-1) po = poh[3];
                    else po = psr[r-2];
                    float pn = byr[r]*po + ayr[r]*dwdy;
                    if (y < 0 || y >= NP) pn = 0.0f;
                    py[r] = pn;
                }
            }
            #pragma unroll
            for (int r2 = 0; r2 < RN_MAX; r2++) {
                if (r2 < RN) {
                    psr[r2] = py[r2+2];
                    if (ayr[r2+2] != 0.0f)
                        pynew[IDX(yb + r2, x)] = py[r2+2];
                }
            }

            #pragma unroll
            for (int r2 = 0; r2 < RN_MAX; r2++) {
                if (r2 < RN) {
                    int m = r2 + 4;
                    int y = yb + r2;
                    float d2y = (C2C*c[m] + C2A*(c[m-1]+c[m+1]) + C2B*(c[m-2]+c[m+2])) * iH2;
                    float dpy = (C1A*(py[r2+3]-py[r2+1]) + C1B*(py[r2+4]-py[r2])) * iH;
                    float s1  = d2y + dpy;
                    float zyv = byr[r2+2]*zyr[r2] + ayr[r2+2]*s1;
                    zyr[r2] = zyv;
                    float lap = s1 + zyv + sxa[r2];
                    float wnew = 2.0f*c[m] - wold[r2] + v2r[r2]*lap;
                    if (srow[r2]) {
                        int key = (y << 9) | x;
                        #pragma unroll
                        for (int j = 0; j < NSRCc; j++)
                            if (sh_key[j] == key) wnew += sh_scale[j] * amp_s[j*NTc + t];
                    }
                    wold[r2] = c[m];
                    wst[IDX(y, x)] = wnew;
                    for (int j = 0; j < nrec; j++)
                        if (sh_rr2[j] == RLO + r2 && sh_rx[j] == x)
                            out[sh_ro[j]*NTc + t] = wnew;
                }
            }
        }
        __syncthreads();   // all stores issued by all threads

        // ---- Post progress: this CTA completed step t (reads AND writes) ----
        if (tid == 0) {
            st_rel(my_arr, (unsigned)(t + 2));
        }
        cur ^= 1;
    }
}

extern "C" void kernel_launch(void* const* d_in, const int* in_sizes, int n_in,
                              void* d_out, int out_size)
{
    const float* v    = (const float*)d_in[0];
    const float* amp  = (const float*)d_in[1];
    const void*  sloc = d_in[2];
    const void*  rloc = d_in[3];
    wave_kernel<<<NCTA, TPB>>>(v, amp, sloc, rloc, (float*)d_out);
}

// round 14
// speedup vs baseline: 2.0462x; 1.3295x over previous
#include <cuda_runtime.h>
#include <math.h>

// Problem constants
#define NYg    256
#define PMLc   20
#define PADc   22          // PML + FD_PAD
#define NP     300         // NYP == NXP
#define SXc    320         // padded row stride (floats)
#define Gc     4           // zero guard ring width
#define ARc    (NP + 2*Gc) // 308 rows allocated
#define Fc     (ARc*SXc)   // floats per field = 98560
#define NTc    250
#define NSHOTc 2
#define NSRCc  8
#define NRECc  64

#define DTc 0.0005f
#define Hc  5.0f

// Persistent-kernel config
#define NCTA  120           // compute CTAs
#define TPB   640           // two 320-thread row-groups per CTA
#define CPS   (NCTA/NSHOTc) // 60 CTAs per shot
#define RPC   (NP/CPS)      // 5 rows per CTA

// Per-shot fields: w0,w1,py0,py1 (psix in smem, zeta/wfm in regs). v2 -> field 8
__device__ float g_state[9*Fc];
__device__ float g_a[NP];
__device__ float g_b[NP];
__device__ unsigned g_arr[NCTA*32];   // progress counters (128B lines)
__device__ unsigned g_go[NCTA*32];    // init-barrier release only

__device__ __forceinline__ int IDX(int y, int x) { return (y+Gc)*SXc + (x+Gc); }

__device__ __forceinline__ unsigned ld_acq(const unsigned* p) {
    unsigned v;
    asm volatile("ld.acquire.gpu.u32 %0, [%1];" : "=r"(v) : "l"(p));
    return v;
}
__device__ __forceinline__ void st_rel(unsigned* p, unsigned v) {
    asm volatile("st.release.gpu.u32 [%0], %1;" :: "l"(p), "r"(v) : "memory");
}
__device__ __forceinline__ void st_rlx(unsigned* p, unsigned v) {
    asm volatile("st.relaxed.gpu.u32 [%0], %1;" :: "l"(p), "r"(v) : "memory");
}

// One-time global init barrier (see R12 notes: replay-safe; leaves all
// g_arr slots == 1 so subsequent monotone >= waits see only this launch).
__device__ __forceinline__ void init_bar(int cta) {
    __syncthreads();
    if (cta == 0) {
        if (threadIdx.x >= 1 && threadIdx.x < NCTA) {
            while (ld_acq(&g_arr[threadIdx.x*32]) != 1u) { }
        }
        __syncthreads();
        if (threadIdx.x >= 1 && threadIdx.x < NCTA) st_rel(&g_go[threadIdx.x*32], 1u);
        if (threadIdx.x == 0) st_rel(&g_arr[0], 1u);
        __syncthreads();
    } else {
        if (threadIdx.x == 0) {
            st_rlx(&g_go[cta*32], 0u);       // kill stale release value
            st_rel(&g_arr[cta*32], 1u);
            while (ld_acq(&g_go[cta*32]) != 1u) { }
        }
        __syncthreads();
    }
}

// Fully specialized per-group time loop. G=0 owns local rows 0..2,
// G=1 owns local rows 3..4. Named barriers:
//   bar 1+G (320 threads): group-local (psix taps, wait release)
//   bar 0   (640 threads): full CTA (store drain before arrival post)
// Divergent-code-path named barriers are the standard warp-specialization
// pattern (arrival counting is per barrier id, not per PC).
template<int G>
__device__ __forceinline__ void run_loop(
    int x, int y0, bool has_up, bool has_dn,
    float* __restrict__ wbase, float* __restrict__ pybase,
    const float* __restrict__ v2, const float* __restrict__ amp_s,
    float* __restrict__ out,
    float (*psix_s)[SXc],
    const int* __restrict__ sh_key, const float* __restrict__ sh_scale,
    int nrec, const int* __restrict__ sh_rr2, const int* __restrict__ sh_rx,
    const int* __restrict__ sh_ro,
    unsigned* my_arr, const unsigned* up_arr, const unsigned* dn_arr)
{
    constexpr int RLO   = G ? 3 : 0;
    constexpr int RN    = G ? 2 : 3;
    constexpr int PR    = RN + 4;     // psiy rows: yb-2 .. yb+RN+1
    constexpr int CN    = RN + 8;     // column rows: yb-4 .. yb+RN+3
    constexpr int OWNLO = 4 - RLO;    // c-index of first own-CTA row

    const int  yb  = y0 + RLO;
    const bool act = (x < NP);

    const float iH  = 1.0f / Hc;
    const float iH2 = 1.0f / (Hc*Hc);
    const float C1A =  0.66666666666666666f, C1B = -0.08333333333333333f;
    const float C2A =  1.33333333333333333f, C2B = -0.08333333333333333f, C2C = -2.5f;

    float ayr[PR], byr[PR];
    #pragma unroll
    for (int r = 0; r < PR; r++) {
        int y = yb - 2 + r;
        bool in = (y >= 0 && y < NP);
        ayr[r] = in ? g_a[y] : 0.0f;
        byr[r] = in ? g_b[y] : 0.0f;
    }
    const float axv = act ? g_a[x] : 0.0f;
    const float bxv = act ? g_b[x] : 0.0f;

    // Halo-load pruning: c[0],c[1],c[CN-2],c[CN-1] feed ONLY halo psiy rows;
    // if those rows' a==0, psiy there is identically 0 -> skip the loads.
    const bool needL0 = (ayr[0] != 0.0f);
    const bool needL1 = needL0 || (ayr[1] != 0.0f);
    const bool needH1 = (ayr[PR-2] != 0.0f) || (ayr[PR-1] != 0.0f);
    const bool needH0 = (ayr[PR-1] != 0.0f);

    float v2r[RN];
    #pragma unroll
    for (int r2 = 0; r2 < RN; r2++)
        v2r[r2] = act ? v2[IDX(yb + r2, x)] : 0.0f;

    bool srow[RN];
    #pragma unroll
    for (int r2 = 0; r2 < RN; r2++) {
        bool s = false;
        #pragma unroll
        for (int j = 0; j < NSRCc; j++) s = s || ((sh_key[j] >> 9) == (yb + r2));
        srow[r2] = s;
    }

    float psr[RN], zyr[RN], zxr[RN], wold[RN];
    #pragma unroll
    for (int r2 = 0; r2 < RN; r2++) { psr[r2]=0.f; zyr[r2]=0.f; zxr[r2]=0.f; wold[r2]=0.f; }

    int cur = 0;

    for (int t = 0; t < NTc; t++) {
        const float* wfc = wbase + cur*Fc;
        float*       wst = wbase + (cur^1)*Fc;
        const int pb = t & 1;
        const float* pyold = pybase + (pb^1)*Fc;
        float*       pynew = pybase + pb*Fc;

        float c[CN], d2xs[RN], sxa[RN];

        // ---- Phase A1: own-row x-derivatives + psix update (own data, L1) ----
        if (act) {
            #pragma unroll
            for (int r2 = 0; r2 < RN; r2++) {
                int p = IDX(yb + r2, x);
                float b3 = wfc[p-2], b1 = wfc[p-1], ct = wfc[p];
                float b2 = wfc[p+1], b4 = wfc[p+2];
                c[r2+4] = ct;
                float d2x  = (C2C*ct + C2A*(b1+b2) + C2B*(b3+b4)) * iH2;
                float dwdx = (C1A*(b2-b1) + C1B*(b4-b3)) * iH;
                float pxn  = bxv*psix_s[RLO+r2][x+4] + axv*dwdx;
                psix_s[RLO+r2][x+4] = pxn;
                d2xs[r2] = d2x;
            }
            // other-group rows of this CTA (own data, no sync needed)
            #pragma unroll
            for (int k = 0; k < CN; k++) {
                constexpr bool IS_OWN_CTA = true;  // placeholder for clarity
                (void)IS_OWN_CTA;
                if (k >= OWNLO && k < OWNLO + 5 && !(k >= 4 && k < 4 + RN))
                    c[k] = wfc[IDX(yb - 4 + k, x)];
            }
        }
        asm volatile("bar.sync %0, 320;" :: "n"(G+1) : "memory");  // psix taps

        // ---- Phase A2: dpx, zetax (own data only) ----
        if (act) {
            #pragma unroll
            for (int r2 = 0; r2 < RN; r2++) {
                float dpx = (C1A*(psix_s[RLO+r2][x+5]-psix_s[RLO+r2][x+3])
                           + C1B*(psix_s[RLO+r2][x+6]-psix_s[RLO+r2][x+2])) * iH;
                float zxv = bxv*zxr[r2] + axv*(d2xs[r2] + dpx);
                zxr[r2] = zxv;
                sxa[r2] = d2xs[r2] + dpx + zxv;
            }
        }

        // ---- Neighbor wait (per-group pollsters) ----
        {
            unsigned need = (unsigned)(t + 1);
            if (x == 0  && has_up) { while (ld_acq(up_arr) < need) { } }
            if (x == 32 && has_dn) { while (ld_acq(dn_arr) < need) { } }
        }
        asm volatile("bar.sync %0, 320;" :: "n"(G+1) : "memory");  // group release

        // ---- Phase B: halo loads + y-path + combine + stores ----
        if (act) {
            #pragma unroll
            for (int k = 0; k < CN; k++) {
                bool own = (k >= OWNLO) && (k < OWNLO + 5);
                if (!own) {
                    if (k == 0)
                        c[k] = needL0 ? __ldcg(wfc + IDX(yb - 4 + k, x)) : 0.0f;
                    else if (k == 1)
                        c[k] = needL1 ? __ldcg(wfc + IDX(yb - 4 + k, x)) : 0.0f;
                    else if (k == CN-2)
                        c[k] = needH1 ? __ldcg(wfc + IDX(yb - 4 + k, x)) : 0.0f;
                    else if (k == CN-1)
                        c[k] = needH0 ? __ldcg(wfc + IDX(yb - 4 + k, x)) : 0.0f;
                    else
                        c[k] = __ldcg(wfc + IDX(yb - 4 + k, x));
                }
            }
            // psiy halo (psiy == 0 where a == 0, by induction from zero init)
            float poh[4];
            poh[0] = needL0 ? __ldcg(pyold + IDX(yb-2,    x)) : 0.0f;
            poh[1] = (ayr[1]    != 0.0f) ? __ldcg(pyold + IDX(yb-1,    x)) : 0.0f;
            poh[2] = (ayr[PR-2] != 0.0f) ? __ldcg(pyold + IDX(yb+RN,   x)) : 0.0f;
            poh[3] = needH0 ? __ldcg(pyold + IDX(yb+RN+1, x)) : 0.0f;

            float py[PR];
            #pragma unroll
            for (int r = 0; r < PR; r++) {
                int y = yb - 2 + r;
                float dwdy = (C1A*(c[r+3]-c[r+1]) + C1B*(c[r+4]-c[r])) * iH;
                float po;
                if (r == 0) po = poh[0];
                else if (r == 1) po = poh[1];
                else if (r == PR-2) po = poh[2];
                else if (r == PR-1) po = poh[3];
                else po = psr[r-2];
                float pn = byr[r]*po + ayr[r]*dwdy;
                if (y < 0 || y >= NP) pn = 0.0f;
                py[r] = pn;
            }
            #pragma unroll
            for (int r2 = 0; r2 < RN; r2++) {
                psr[r2] = py[r2+2];
                if (ayr[r2+2] != 0.0f)
                    pynew[IDX(yb + r2, x)] = py[r2+2];
            }

            #pragma unroll
            for (int r2 = 0; r2 < RN; r2++) {
                constexpr int mBase = 4;
                int m = r2 + mBase;
                int y = yb + r2;
                float d2y = (C2C*c[m] + C2A*(c[m-1]+c[m+1]) + C2B*(c[m-2]+c[m+2])) * iH2;
                float dpy = (C1A*(py[r2+3]-py[r2+1]) + C1B*(py[r2+4]-py[r2])) * iH;
                float s1  = d2y + dpy;
                float zyv = byr[r2+2]*zyr[r2] + ayr[r2+2]*s1;
                zyr[r2] = zyv;
                float lap = s1 + zyv + sxa[r2];
                float wnew = 2.0f*c[m] - wold[r2] + v2r[r2]*lap;
                if (srow[r2]) {
                    int key = (y << 9) | x;
                    #pragma unroll
                    for (int j = 0; j < NSRCc; j++)
                        if (sh_key[j] == key) wnew += sh_scale[j] * amp_s[j*NTc + t];
                }
                wold[r2] = c[m];
                wst[IDX(y, x)] = wnew;
                for (int j = 0; j < nrec; j++)
                    if (sh_rr2[j] == RLO + r2 && sh_rx[j] == x)
                        out[sh_ro[j]*NTc + t] = wnew;
            }
        }

        asm volatile("bar.sync 0, %0;" :: "n"(TPB) : "memory");  // full-CTA drain

        if (G == 0 && x == 0) {
            st_rel(my_arr, (unsigned)(t + 2));   // covers whole CTA via bar 0
        }
        cur ^= 1;
    }
}

extern "C" __global__ void __launch_bounds__(TPB, 1)
wave_kernel(const float* __restrict__ v,
            const float* __restrict__ amp,
            const void*  __restrict__ sloc,
            const void*  __restrict__ rloc,
            float* __restrict__ out)
{
    const int cta = blockIdx.x, tid = threadIdx.x;
    const int gt = cta*TPB + tid, GT = NCTA*TPB;

    // ---------------- init (every launch: deterministic) ----------------
    for (int i = gt; i < 8*Fc; i += GT) g_state[i] = 0.0f;

    for (int i = gt; i < NP; i += GT) {
        float fi = (float)i;
        float frac = fmaxf((float)PADc - fi, fi - (float)(NP - PADc - 1)) / (float)PMLc;
        frac = fminf(fmaxf(frac, 0.0f), 1.0f);
        float smax = 3.0f * 4000.0f * logf(1000.0f) / (2.0f * (float)PMLc * Hc);
        float sig  = smax * frac * frac;
        float alp  = 3.14159265358979f * 25.0f * (1.0f - frac);
        float bb   = expf(-(sig + alp) * DTc);
        g_b[i] = bb;
        g_a[i] = sig / (sig + alp + 1e-9f) * (bb - 1.0f);
    }

    for (int i = gt; i < NP*NP; i += GT) {
        int y = i / NP, x = i - y*NP;
        int vy = min(max(y - PADc, 0), NYg - 1);
        int vx = min(max(x - PADc, 0), NYg - 1);
        float vv = v[vy*NYg + vx];
        g_state[8*Fc + IDX(y,x)] = vv * vv * (DTc*DTc);
    }

    const int shot = cta / CPS;
    const int pos  = cta % CPS;
    const int y0   = pos * RPC;
    const bool has_up = (pos > 0);
    const bool has_dn = (pos < CPS - 1);

    __shared__ int   sh_key[NSRCc];
    __shared__ float sh_scale[NSRCc];
    __shared__ float psix_s[RPC][SXc];  // persistent psix (x-guards 0)
    __shared__ int   sh_rn;
    __shared__ int   sh_rr2[NRECc];
    __shared__ int   sh_rx[NRECc];
    __shared__ int   sh_ro[NRECc];

    for (int i = tid; i < RPC*SXc; i += TPB) ((float*)psix_s)[i] = 0.0f;

    if (tid < NSRCc) {
        const unsigned* w32 = (const unsigned*)sloc;
        bool is64 = true;
        for (int i = 1; i < NSHOTc*NSRCc*2; i += 2)
            if (w32[i] != 0u) { is64 = false; break; }
        int e = (shot*NSRCc + tid) * 2;
        int sy, sx;
        if (is64) { sy = (int)w32[2*e]; sx = (int)w32[2*(e+1)]; }
        else      { const int* w = (const int*)sloc; sy = w[e]; sx = w[e+1]; }
        float vv = v[sy*NYg + sx];
        sh_key[tid]   = ((sy + PADc) << 9) | (sx + PADc);
        sh_scale[tid] = vv * vv * (DTc*DTc);
    }
    if (tid == 0) {
        const unsigned* w32 = (const unsigned*)rloc;
        bool is64 = true;
        for (int i = 1; i < NSHOTc*NRECc*2; i += 2)
            if (w32[i] != 0u) { is64 = false; break; }
        int n = 0;
        for (int rr = 0; rr < NRECc; rr++) {
            int e = (shot*NRECc + rr) * 2;
            int ry, rx;
            if (is64) { ry = (int)w32[2*e]; rx = (int)w32[2*(e+1)]; }
            else      { const int* w = (const int*)rloc; ry = w[e]; rx = w[e+1]; }
            int yp = ry + PADc;
            if (yp >= y0 && yp < y0 + RPC) {
                sh_rr2[n] = yp - y0;
                sh_rx[n]  = rx + PADc;
                sh_ro[n]  = shot*NRECc + rr;
                n++;
            }
        }
        sh_rn = n;
    }

    init_bar(cta);   // init visible everywhere; all g_arr slots == 1

    float* wbase  = g_state + shot*4*Fc;
    float* pybase = wbase + 2*Fc;
    const float* v2 = g_state + 8*Fc;
    const float* amp_s = amp + shot*NSRCc*NTc;
    const int nrec = sh_rn;

    unsigned* my_arr = &g_arr[cta*32];
    const unsigned* up_arr = has_up ? &g_arr[(cta-1)*32] : my_arr;
    const unsigned* dn_arr = has_dn ? &g_arr[(cta+1)*32] : my_arr;

    if (tid < 320) {
        run_loop<0>(tid, y0, has_up, has_dn, wbase, pybase, v2, amp_s,
                    out, psix_s, sh_key, sh_scale, nrec, sh_rr2, sh_rx, sh_ro,
                    my_arr, up_arr, dn_arr);
    } else {
        run_loop<1>(tid - 320, y0, has_up, has_dn, wbase, pybase, v2, amp_s,
                    out, psix_s, sh_key, sh_scale, nrec, sh_rr2, sh_rx, sh_ro,
                    my_arr, up_arr, dn_arr);
    }
}

extern "C" void kernel_launch(void* const* d_in, const int* in_sizes, int n_in,
                              void* d_out, int out_size)
{
    const float* v    = (const float*)d_in[0];
    const float* amp  = (const float*)d_in[1];
    const void*  sloc = d_in[2];
    const void*  rloc = d_in[3];
    wave_kernel<<<NCTA, TPB>>>(v, amp, sloc, rloc, (float*)d_out);
}

// round 15
// speedup vs baseline: 2.1932x; 1.0718x over previous
#include <cuda_runtime.h>
#include <math.h>

// Problem constants
#define NYg    256
#define PMLc   20
#define PADc   22          // PML + FD_PAD
#define NP     300         // NYP == NXP
#define SXc    320         // padded row stride (floats)
#define Gc     4           // zero guard ring width
#define ARc    (NP + 2*Gc) // 308 rows allocated
#define Fc     (ARc*SXc)   // floats per field = 98560
#define NTc    250
#define NSHOTc 2
#define NSRCc  8
#define NRECc  64

#define DTc 0.0005f
#define Hc  5.0f

// Persistent-kernel config: fine decomposition, 2 CTAs on some SMs
#define NCTA  200           // 100 CTAs per shot
#define TPB   320
#define CPS   (NCTA/NSHOTc) // 100
#define RPC   3             // rows per CTA (uniform)
#define PR    (RPC+4)       // 7 psiy rows: y0-2 .. y0+4
#define CN    (RPC+8)       // 11 column rows: y0-4 .. y0+6

// Per-shot fields: w0,w1,py0,py1 (psix in smem, zeta/wfm in regs). v2 -> field 8
__device__ float g_state[9*Fc];
__device__ float g_a[NP];
__device__ float g_b[NP];
__device__ unsigned g_arr[NCTA*32];   // progress counters (128B lines)
__device__ unsigned g_go[NCTA*32];    // init-barrier release only

__device__ __forceinline__ int IDX(int y, int x) { return (y+Gc)*SXc + (x+Gc); }

__device__ __forceinline__ unsigned ld_acq(const unsigned* p) {
    unsigned v;
    asm volatile("ld.acquire.gpu.u32 %0, [%1];" : "=r"(v) : "l"(p));
    return v;
}
__device__ __forceinline__ void st_rel(unsigned* p, unsigned v) {
    asm volatile("st.release.gpu.u32 [%0], %1;" :: "l"(p), "r"(v) : "memory");
}
__device__ __forceinline__ void st_rlx(unsigned* p, unsigned v) {
    asm volatile("st.relaxed.gpu.u32 [%0], %1;" :: "l"(p), "r"(v) : "memory");
}

// One-time global init barrier (replay-safe; see R12 notes). Leaves all
// g_arr slots == 1 so subsequent monotone >= waits see only this launch.
__device__ __forceinline__ void init_bar(int cta) {
    __syncthreads();
    if (cta == 0) {
        if (threadIdx.x >= 1 && threadIdx.x < NCTA) {
            while (ld_acq(&g_arr[threadIdx.x*32]) != 1u) { }
        }
        __syncthreads();
        if (threadIdx.x >= 1 && threadIdx.x < NCTA) st_rel(&g_go[threadIdx.x*32], 1u);
        if (threadIdx.x == 0) st_rel(&g_arr[0], 1u);
        __syncthreads();
    } else {
        if (threadIdx.x == 0) {
            st_rlx(&g_go[cta*32], 0u);       // kill stale release value
            st_rel(&g_arr[cta*32], 1u);
            while (ld_acq(&g_go[cta*32]) != 1u) { }
        }
        __syncthreads();
    }
}

extern "C" __global__ void __launch_bounds__(TPB, 2)
wave_kernel(const float* __restrict__ v,
            const float* __restrict__ amp,
            const void*  __restrict__ sloc,
            const void*  __restrict__ rloc,
            float* __restrict__ out)
{
    const int cta = blockIdx.x, tid = threadIdx.x;
    const int gt = cta*TPB + tid, GT = NCTA*TPB;

    // ---------------- init (every launch: deterministic) ----------------
    for (int i = gt; i < 8*Fc; i += GT) g_state[i] = 0.0f;

    for (int i = gt; i < NP; i += GT) {
        float fi = (float)i;
        float frac = fmaxf((float)PADc - fi, fi - (float)(NP - PADc - 1)) / (float)PMLc;
        frac = fminf(fmaxf(frac, 0.0f), 1.0f);
        float smax = 3.0f * 4000.0f * logf(1000.0f) / (2.0f * (float)PMLc * Hc);
        float sig  = smax * frac * frac;
        float alp  = 3.14159265358979f * 25.0f * (1.0f - frac);
        float bb   = expf(-(sig + alp) * DTc);
        g_b[i] = bb;
        g_a[i] = sig / (sig + alp + 1e-9f) * (bb - 1.0f);
    }

    for (int i = gt; i < NP*NP; i += GT) {
        int y = i / NP, x = i - y*NP;
        int vy = min(max(y - PADc, 0), NYg - 1);
        int vx = min(max(x - PADc, 0), NYg - 1);
        float vv = v[vy*NYg + vx];
        g_state[8*Fc + IDX(y,x)] = vv * vv * (DTc*DTc);
    }

    const int shot = cta / CPS;
    const int pos  = cta % CPS;
    const int y0   = pos * RPC;
    const bool has_up = (pos > 0);
    const bool has_dn = (pos < CPS - 1);

    __shared__ int   sh_key[NSRCc];
    __shared__ float sh_scale[NSRCc];
    __shared__ float psix_s[RPC][SXc];  // persistent psix (x-guards 0)
    __shared__ int   sh_rn;
    __shared__ int   sh_rr2[NRECc];
    __shared__ int   sh_rx[NRECc];
    __shared__ int   sh_ro[NRECc];

    for (int i = tid; i < RPC*SXc; i += TPB) ((float*)psix_s)[i] = 0.0f;

    if (tid < NSRCc) {
        const unsigned* w32 = (const unsigned*)sloc;
        bool is64 = true;
        for (int i = 1; i < NSHOTc*NSRCc*2; i += 2)
            if (w32[i] != 0u) { is64 = false; break; }
        int e = (shot*NSRCc + tid) * 2;
        int sy, sx;
        if (is64) { sy = (int)w32[2*e]; sx = (int)w32[2*(e+1)]; }
        else      { const int* w = (const int*)sloc; sy = w[e]; sx = w[e+1]; }
        float vv = v[sy*NYg + sx];
        sh_key[tid]   = ((sy + PADc) << 9) | (sx + PADc);
        sh_scale[tid] = vv * vv * (DTc*DTc);
    }
    if (tid == 0) {
        const unsigned* w32 = (const unsigned*)rloc;
        bool is64 = true;
        for (int i = 1; i < NSHOTc*NRECc*2; i += 2)
            if (w32[i] != 0u) { is64 = false; break; }
        int n = 0;
        for (int rr = 0; rr < NRECc; rr++) {
            int e = (shot*NRECc + rr) * 2;
            int ry, rx;
            if (is64) { ry = (int)w32[2*e]; rx = (int)w32[2*(e+1)]; }
            else      { const int* w = (const int*)rloc; ry = w[e]; rx = w[e+1]; }
            int yp = ry + PADc;
            if (yp >= y0 && yp < y0 + RPC) {
                sh_rr2[n] = yp - y0;
                sh_rx[n]  = rx + PADc;
                sh_ro[n]  = shot*NRECc + rr;
                n++;
            }
        }
        sh_rn = n;
    }

    init_bar(cta);   // init visible everywhere; all g_arr slots == 1

    // ---------------- per-thread setup ----------------
    float* wbase  = g_state + shot*4*Fc;
    float* pybase = wbase + 2*Fc;
    const float* v2 = g_state + 8*Fc;
    const float* amp_s = amp + shot*NSRCc*NTc;
    const int nrec = sh_rn;

    const float iH  = 1.0f / Hc;
    const float iH2 = 1.0f / (Hc*Hc);
    const float C1A =  0.66666666666666666f, C1B = -0.08333333333333333f;
    const float C2A =  1.33333333333333333f, C2B = -0.08333333333333333f, C2C = -2.5f;

    const int  x   = tid;
    const bool act = (x < NP);

    float ayr[PR], byr[PR];
    #pragma unroll
    for (int r = 0; r < PR; r++) {
        int y = y0 - 2 + r;
        bool in = (y >= 0 && y < NP);
        ayr[r] = in ? g_a[y] : 0.0f;
        byr[r] = in ? g_b[y] : 0.0f;
    }
    const float axv = act ? g_a[x] : 0.0f;
    const float bxv = act ? g_b[x] : 0.0f;

    // Halo-load pruning: c[0],c[1],c[CN-2],c[CN-1] feed ONLY halo psiy rows;
    // if those rows' a==0, psiy there is identically 0 -> skip the loads.
    const bool needL0 = (ayr[0] != 0.0f);
    const bool needL1 = needL0 || (ayr[1] != 0.0f);
    const bool needH1 = (ayr[PR-2] != 0.0f) || (ayr[PR-1] != 0.0f);
    const bool needH0 = (ayr[PR-1] != 0.0f);

    float v2r[RPC];
    #pragma unroll
    for (int r2 = 0; r2 < RPC; r2++)
        v2r[r2] = act ? v2[IDX(y0 + r2, x)] : 0.0f;

    bool srow[RPC];
    #pragma unroll
    for (int r2 = 0; r2 < RPC; r2++) {
        bool s = false;
        #pragma unroll
        for (int j = 0; j < NSRCc; j++) s = s || ((sh_key[j] >> 9) == (y0 + r2));
        srow[r2] = s;
    }

    float psr[RPC], zyr[RPC], zxr[RPC], wold[RPC];
    #pragma unroll
    for (int r2 = 0; r2 < RPC; r2++) { psr[r2]=0.f; zyr[r2]=0.f; zxr[r2]=0.f; wold[r2]=0.f; }

    int cur = 0;
    unsigned* my_arr = &g_arr[cta*32];
    const unsigned* up_arr = has_up ? &g_arr[(cta-1)*32] : my_arr;
    const unsigned* dn_arr = has_dn ? &g_arr[(cta+1)*32] : my_arr;

    // ------------- time loop: split-phase + neighbor-only sync -------------
    // arr[i]: 1 after init; t+2 after CTA i completed step t (reads+writes).
    // Before Phase B of step t, wait arr[up/dn] >= t+1.
    for (int t = 0; t < NTc; t++) {
        const float* wfc = wbase + cur*Fc;
        float*       wst = wbase + (cur^1)*Fc;
        const int pb = t & 1;
        const float* pyold = pybase + (pb^1)*Fc;
        float*       pynew = pybase + pb*Fc;

        float c[CN], d2xs[RPC], sxa[RPC];

        // ---- Phase A1: own-row x-derivatives + psix update (own data, L1) ----
        if (act) {
            #pragma unroll
            for (int r2 = 0; r2 < RPC; r2++) {
                int p = IDX(y0 + r2, x);
                float b3 = wfc[p-2], b1 = wfc[p-1], ct = wfc[p];
                float b2 = wfc[p+1], b4 = wfc[p+2];
                c[r2+4] = ct;
                float d2x  = (C2C*ct + C2A*(b1+b2) + C2B*(b3+b4)) * iH2;
                float dwdx = (C1A*(b2-b1) + C1B*(b4-b3)) * iH;
                float pxn  = bxv*psix_s[r2][x+4] + axv*dwdx;
                psix_s[r2][x+4] = pxn;
                d2xs[r2] = d2x;
            }
        }
        __syncthreads();   // psix taps ready

        // ---- Phase A2: dpx, zetax (own data only) ----
        if (act) {
            #pragma unroll
            for (int r2 = 0; r2 < RPC; r2++) {
                float dpx = (C1A*(psix_s[r2][x+5]-psix_s[r2][x+3])
                           + C1B*(psix_s[r2][x+6]-psix_s[r2][x+2])) * iH;
                float zxv = bxv*zxr[r2] + axv*(d2xs[r2] + dpx);
                zxr[r2] = zxv;
                sxa[r2] = d2xs[r2] + dpx + zxv;
            }
        }

        // ---- Neighbor wait ----
        {
            unsigned need = (unsigned)(t + 1);
            if (tid == 0  && has_up) { while (ld_acq(up_arr) < need) { } }
            if (tid == 32 && has_dn) { while (ld_acq(dn_arr) < need) { } }
        }
        __syncthreads();

        // ---- Phase B: halo loads + y-path + combine + stores ----
        if (act) {
            // halo rows of the column (neighbor CTA data, L2); k=2,3,7,8 always
            #pragma unroll
            for (int k = 0; k < CN; k++) {
                bool own = (k >= 4) && (k < 4 + RPC);
                if (!own) {
                    if (k == 0)
                        c[k] = needL0 ? __ldcg(wfc + IDX(y0 - 4 + k, x)) : 0.0f;
                    else if (k == 1)
                        c[k] = needL1 ? __ldcg(wfc + IDX(y0 - 4 + k, x)) : 0.0f;
                    else if (k == CN-2)
                        c[k] = needH1 ? __ldcg(wfc + IDX(y0 - 4 + k, x)) : 0.0f;
                    else if (k == CN-1)
                        c[k] = needH0 ? __ldcg(wfc + IDX(y0 - 4 + k, x)) : 0.0f;
                    else
                        c[k] = __ldcg(wfc + IDX(y0 - 4 + k, x));
                }
            }
            // psiy halo (psiy == 0 where a == 0, by induction from zero init)
            float poh[4];
            poh[0] = needL0 ? __ldcg(pyold + IDX(y0-2,     x)) : 0.0f;
            poh[1] = (ayr[1]    != 0.0f) ? __ldcg(pyold + IDX(y0-1,     x)) : 0.0f;
            poh[2] = (ayr[PR-2] != 0.0f) ? __ldcg(pyold + IDX(y0+RPC,   x)) : 0.0f;
            poh[3] = needH0 ? __ldcg(pyold + IDX(y0+RPC+1, x)) : 0.0f;

            float py[PR];
            #pragma unroll
            for (int r = 0; r < PR; r++) {
                int y = y0 - 2 + r;
                float dwdy = (C1A*(c[r+3]-c[r+1]) + C1B*(c[r+4]-c[r])) * iH;
                float po;
                if (r == 0) po = poh[0];
                else if (r == 1) po = poh[1];
                else if (r == PR-2) po = poh[2];
                else if (r == PR-1) po = poh[3];
                else po = psr[r-2];
                float pn = byr[r]*po + ayr[r]*dwdy;
                if (y < 0 || y >= NP) pn = 0.0f;
                py[r] = pn;
            }
            #pragma unroll
            for (int r2 = 0; r2 < RPC; r2++) {
                psr[r2] = py[r2+2];
                if (ayr[r2+2] != 0.0f)
                    pynew[IDX(y0 + r2, x)] = py[r2+2];
            }

            #pragma unroll
            for (int r2 = 0; r2 < RPC; r2++) {
                int m = r2 + 4;
                int y = y0 + r2;
                float d2y = (C2C*c[m] + C2A*(c[m-1]+c[m+1]) + C2B*(c[m-2]+c[m+2])) * iH2;
                float dpy = (C1A*(py[r2+3]-py[r2+1]) + C1B*(py[r2+4]-py[r2])) * iH;
                float s1  = d2y + dpy;
                float zyv = byr[r2+2]*zyr[r2] + ayr[r2+2]*s1;
                zyr[r2] = zyv;
                float lap = s1 + zyv + sxa[r2];
                float wnew = 2.0f*c[m] - wold[r2] + v2r[r2]*lap;
                if (srow[r2]) {
                    int key = (y << 9) | x;
                    #pragma unroll
                    for (int j = 0; j < NSRCc; j++)
                        if (sh_key[j] == key) wnew += sh_scale[j] * amp_s[j*NTc + t];
                }
                wold[r2] = c[m];
                wst[IDX(y, x)] = wnew;
                for (int j = 0; j < nrec; j++)
                    if (sh_rr2[j] == r2 && sh_rx[j] == x)
                        out[sh_ro[j]*NTc + t] = wnew;
            }
        }
        __syncthreads();   // store drain

        if (tid == 0) {
            st_rel(my_arr, (unsigned)(t + 2));
        }
        cur ^= 1;
    }
}

extern "C" void kernel_launch(void* const* d_in, const int* in_sizes, int n_in,
                              void* d_out, int out_size)
{
    const float* v    = (const float*)d_in[0];
    const float* amp  = (const float*)d_in[1];
    const void*  sloc = d_in[2];
    const void*  rloc = d_in[3];
    wave_kernel<<<NCTA, TPB>>>(v, amp, sloc, rloc, (float*)d_out);
}

// round 16
// speedup vs baseline: 2.2770x; 1.0382x over previous
#include <cuda_runtime.h>
#include <math.h>

// Problem constants
#define NYg    256
#define PMLc   20
#define PADc   22          // PML + FD_PAD
#define NP     300         // NYP == NXP
#define SXc    320         // padded row stride (floats)
#define Gc     4           // zero guard ring width
#define ARc    (NP + 2*Gc) // 308 rows allocated
#define Fc     (ARc*SXc)   // floats per field = 98560
#define NTc    250
#define NSHOTc 2
#define NSRCc  8
#define NRECc  64

#define DTc 0.0005f
#define Hc  5.0f

// Persistent-kernel config: 296 CTAs = exactly 2 per SM (148 SMs), single wave
#define NCTA  296
#define TPB   320
#define CPS   (NCTA/NSHOTc) // 148 CTAs per shot
// Per shot: CTAs 0..143 own 2 rows (y0 = pos*2), CTAs 144..147 own 3 rows
// (y0 = 288 + (pos-144)*3). 144*2 + 4*3 = 300 ✓
#define RMAX  3

// Per-shot fields: w0,w1,py0,py1 (psix in smem, zeta/wfm in regs). v2 -> field 8
__device__ float g_state[9*Fc];
__device__ float g_a[NP];
__device__ float g_b[NP];
__device__ unsigned g_arr[NCTA*32];   // progress counters (128B lines)
__device__ unsigned g_go[NCTA*32];    // init-barrier release only

__device__ __forceinline__ int IDX(int y, int x) { return (y+Gc)*SXc + (x+Gc); }

__device__ __forceinline__ unsigned ld_acq(const unsigned* p) {
    unsigned v;
    asm volatile("ld.acquire.gpu.u32 %0, [%1];" : "=r"(v) : "l"(p));
    return v;
}
__device__ __forceinline__ void st_rel(unsigned* p, unsigned v) {
    asm volatile("st.release.gpu.u32 [%0], %1;" :: "l"(p), "r"(v) : "memory");
}
__device__ __forceinline__ void st_rlx(unsigned* p, unsigned v) {
    asm volatile("st.relaxed.gpu.u32 [%0], %1;" :: "l"(p), "r"(v) : "memory");
}

// One-time global init barrier (replay-safe; see R12 notes). Leaves all
// g_arr slots == 1 so subsequent monotone >= waits see only this launch.
__device__ __forceinline__ void init_bar(int cta) {
    __syncthreads();
    if (cta == 0) {
        if (threadIdx.x >= 1 && threadIdx.x < NCTA) {
            while (ld_acq(&g_arr[threadIdx.x*32]) != 1u) { }
        }
        __syncthreads();
        if (threadIdx.x >= 1 && threadIdx.x < NCTA) st_rel(&g_go[threadIdx.x*32], 1u);
        if (threadIdx.x == 0) st_rel(&g_arr[0], 1u);
        __syncthreads();
    } else {
        if (threadIdx.x == 0) {
            st_rlx(&g_go[cta*32], 0u);       // kill stale release value
            st_rel(&g_arr[cta*32], 1u);
            while (ld_acq(&g_go[cta*32]) != 1u) { }
        }
        __syncthreads();
    }
}

// Time loop, fully specialized on rows-per-CTA R.
template<int R>
__device__ __forceinline__ void run_loop(
    int x, int y0, bool has_up, bool has_dn,
    float* __restrict__ wbase, float* __restrict__ pybase,
    const float* __restrict__ v2, const float* __restrict__ amp_s,
    float* __restrict__ out,
    float (*psix_s)[SXc],
    const int* __restrict__ sh_key, const float* __restrict__ sh_scale,
    int nrec, const int* __restrict__ sh_rr2, const int* __restrict__ sh_rx,
    const int* __restrict__ sh_ro,
    unsigned* my_arr, const unsigned* up_arr, const unsigned* dn_arr)
{
    constexpr int PR = R + 4;     // psiy rows: y0-2 .. y0+R+1
    constexpr int CN = R + 8;     // column rows: y0-4 .. y0+R+3

    const bool act = (x < NP);

    const float iH  = 1.0f / Hc;
    const float iH2 = 1.0f / (Hc*Hc);
    const float C1A =  0.66666666666666666f, C1B = -0.08333333333333333f;
    const float C2A =  1.33333333333333333f, C2B = -0.08333333333333333f, C2C = -2.5f;

    float ayr[PR], byr[PR];
    #pragma unroll
    for (int r = 0; r < PR; r++) {
        int y = y0 - 2 + r;
        bool in = (y >= 0 && y < NP);
        ayr[r] = in ? g_a[y] : 0.0f;
        byr[r] = in ? g_b[y] : 0.0f;
    }
    const float axv = act ? g_a[x] : 0.0f;
    const float bxv = act ? g_b[x] : 0.0f;

    // Halo-load pruning: c[0],c[1],c[CN-2],c[CN-1] feed ONLY halo psiy rows;
    // if those rows' a==0, psiy there is identically 0 -> skip the loads.
    const bool needL0 = (ayr[0] != 0.0f);
    const bool needL1 = needL0 || (ayr[1] != 0.0f);
    const bool needH1 = (ayr[PR-2] != 0.0f) || (ayr[PR-1] != 0.0f);
    const bool needH0 = (ayr[PR-1] != 0.0f);

    float v2r[R];
    #pragma unroll
    for (int r2 = 0; r2 < R; r2++)
        v2r[r2] = act ? v2[IDX(y0 + r2, x)] : 0.0f;

    bool srow[R];
    #pragma unroll
    for (int r2 = 0; r2 < R; r2++) {
        bool s = false;
        #pragma unroll
        for (int j = 0; j < NSRCc; j++) s = s || ((sh_key[j] >> 9) == (y0 + r2));
        srow[r2] = s;
    }

    float psr[R], zyr[R], zxr[R], wold[R];
    #pragma unroll
    for (int r2 = 0; r2 < R; r2++) { psr[r2]=0.f; zyr[r2]=0.f; zxr[r2]=0.f; wold[r2]=0.f; }

    int cur = 0;

    for (int t = 0; t < NTc; t++) {
        const float* wfc = wbase + cur*Fc;
        float*       wst = wbase + (cur^1)*Fc;
        const int pb = t & 1;
        const float* pyold = pybase + (pb^1)*Fc;
        float*       pynew = pybase + pb*Fc;

        float c[CN], d2xs[R], sxa[R];

        // ---- Phase A1: own-row x-derivatives + psix update (own data, L1) ----
        if (act) {
            #pragma unroll
            for (int r2 = 0; r2 < R; r2++) {
                int p = IDX(y0 + r2, x);
                float b3 = wfc[p-2], b1 = wfc[p-1], ct = wfc[p];
                float b2 = wfc[p+1], b4 = wfc[p+2];
                c[r2+4] = ct;
                float d2x  = (C2C*ct + C2A*(b1+b2) + C2B*(b3+b4)) * iH2;
                float dwdx = (C1A*(b2-b1) + C1B*(b4-b3)) * iH;
                float pxn  = bxv*psix_s[r2][x+4] + axv*dwdx;
                psix_s[r2][x+4] = pxn;
                d2xs[r2] = d2x;
            }
        }
        __syncthreads();   // psix taps ready

        // ---- Phase A2: dpx, zetax (own data only) ----
        if (act) {
            #pragma unroll
            for (int r2 = 0; r2 < R; r2++) {
                float dpx = (C1A*(psix_s[r2][x+5]-psix_s[r2][x+3])
                           + C1B*(psix_s[r2][x+6]-psix_s[r2][x+2])) * iH;
                float zxv = bxv*zxr[r2] + axv*(d2xs[r2] + dpx);
                zxr[r2] = zxv;
                sxa[r2] = d2xs[r2] + dpx + zxv;
            }
        }

        // ---- Neighbor wait ----
        {
            unsigned need = (unsigned)(t + 1);
            if (x == 0  && has_up) { while (ld_acq(up_arr) < need) { } }
            if (x == 32 && has_dn) { while (ld_acq(dn_arr) < need) { } }
        }
        __syncthreads();

        // ---- Phase B: halo loads + y-path + combine + stores ----
        if (act) {
            #pragma unroll
            for (int k = 0; k < CN; k++) {
                bool own = (k >= 4) && (k < 4 + R);
                if (!own) {
                    if (k == 0)
                        c[k] = needL0 ? __ldcg(wfc + IDX(y0 - 4 + k, x)) : 0.0f;
                    else if (k == 1)
                        c[k] = needL1 ? __ldcg(wfc + IDX(y0 - 4 + k, x)) : 0.0f;
                    else if (k == CN-2)
                        c[k] = needH1 ? __ldcg(wfc + IDX(y0 - 4 + k, x)) : 0.0f;
                    else if (k == CN-1)
                        c[k] = needH0 ? __ldcg(wfc + IDX(y0 - 4 + k, x)) : 0.0f;
                    else
                        c[k] = __ldcg(wfc + IDX(y0 - 4 + k, x));
                }
            }
            // psiy halo (psiy == 0 where a == 0, by induction from zero init)
            float poh[4];
            poh[0] = needL0 ? __ldcg(pyold + IDX(y0-2,   x)) : 0.0f;
            poh[1] = (ayr[1]    != 0.0f) ? __ldcg(pyold + IDX(y0-1,   x)) : 0.0f;
            poh[2] = (ayr[PR-2] != 0.0f) ? __ldcg(pyold + IDX(y0+R,   x)) : 0.0f;
            poh[3] = needH0 ? __ldcg(pyold + IDX(y0+R+1, x)) : 0.0f;

            float py[PR];
            #pragma unroll
            for (int r = 0; r < PR; r++) {
                int y = y0 - 2 + r;
                float dwdy = (C1A*(c[r+3]-c[r+1]) + C1B*(c[r+4]-c[r])) * iH;
                float po;
                if (r == 0) po = poh[0];
                else if (r == 1) po = poh[1];
                else if (r == PR-2) po = poh[2];
                else if (r == PR-1) po = poh[3];
                else po = psr[r-2];
                float pn = byr[r]*po + ayr[r]*dwdy;
                if (y < 0 || y >= NP) pn = 0.0f;
                py[r] = pn;
            }
            #pragma unroll
            for (int r2 = 0; r2 < R; r2++) {
                psr[r2] = py[r2+2];
                if (ayr[r2+2] != 0.0f)
                    pynew[IDX(y0 + r2, x)] = py[r2+2];
            }

            #pragma unroll
            for (int r2 = 0; r2 < R; r2++) {
                int m = r2 + 4;
                int y = y0 + r2;
                float d2y = (C2C*c[m] + C2A*(c[m-1]+c[m+1]) + C2B*(c[m-2]+c[m+2])) * iH2;
                float dpy = (C1A*(py[r2+3]-py[r2+1]) + C1B*(py[r2+4]-py[r2])) * iH;
                float s1  = d2y + dpy;
                float zyv = byr[r2+2]*zyr[r2] + ayr[r2+2]*s1;
                zyr[r2] = zyv;
                float lap = s1 + zyv + sxa[r2];
                float wnew = 2.0f*c[m] - wold[r2] + v2r[r2]*lap;
                if (srow[r2]) {
                    int key = (y << 9) | x;
                    #pragma unroll
                    for (int j = 0; j < NSRCc; j++)
                        if (sh_key[j] == key) wnew += sh_scale[j] * amp_s[j*NTc + t];
                }
                wold[r2] = c[m];
                wst[IDX(y, x)] = wnew;
                for (int j = 0; j < nrec; j++)
                    if (sh_rr2[j] == r2 && sh_rx[j] == x)
                        out[sh_ro[j]*NTc + t] = wnew;
            }
        }
        __syncthreads();   // store drain ordering point

        if (x == 0) {
            st_rel(my_arr, (unsigned)(t + 2));
        }
        cur ^= 1;
    }
}

extern "C" __global__ void __launch_bounds__(TPB, 2)
wave_kernel(const float* __restrict__ v,
            const float* __restrict__ amp,
            const void*  __restrict__ sloc,
            const void*  __restrict__ rloc,
            float* __restrict__ out)
{
    const int cta = blockIdx.x, tid = threadIdx.x;
    const int gt = cta*TPB + tid, GT = NCTA*TPB;

    // ---------------- init (every launch: deterministic) ----------------
    for (int i = gt; i < 8*Fc; i += GT) g_state[i] = 0.0f;

    for (int i = gt; i < NP; i += GT) {
        float fi = (float)i;
        float frac = fmaxf((float)PADc - fi, fi - (float)(NP - PADc - 1)) / (float)PMLc;
        frac = fminf(fmaxf(frac, 0.0f), 1.0f);
        float smax = 3.0f * 4000.0f * logf(1000.0f) / (2.0f * (float)PMLc * Hc);
        float sig  = smax * frac * frac;
        float alp  = 3.14159265358979f * 25.0f * (1.0f - frac);
        float bb   = expf(-(sig + alp) * DTc);
        g_b[i] = bb;
        g_a[i] = sig / (sig + alp + 1e-9f) * (bb - 1.0f);
    }

    for (int i = gt; i < NP*NP; i += GT) {
        int y = i / NP, x = i - y*NP;
        int vy = min(max(y - PADc, 0), NYg - 1);
        int vx = min(max(x - PADc, 0), NYg - 1);
        float vv = v[vy*NYg + vx];
        g_state[8*Fc + IDX(y,x)] = vv * vv * (DTc*DTc);
    }

    const int shot = cta / CPS;
    const int pos  = cta % CPS;
    const bool big = (pos >= 144);          // 3-row CTAs (bottom PML)
    const int y0   = big ? 288 + (pos - 144)*3 : pos*2;
    const int myR  = big ? 3 : 2;
    const bool has_up = (pos > 0);
    const bool has_dn = (pos < CPS - 1);

    __shared__ int   sh_key[NSRCc];
    __shared__ float sh_scale[NSRCc];
    __shared__ float psix_s[RMAX][SXc];  // persistent psix (x-guards 0)
    __shared__ int   sh_rn;
    __shared__ int   sh_rr2[NRECc];
    __shared__ int   sh_rx[NRECc];
    __shared__ int   sh_ro[NRECc];

    for (int i = tid; i < RMAX*SXc; i += TPB) ((float*)psix_s)[i] = 0.0f;

    if (tid < NSRCc) {
        const unsigned* w32 = (const unsigned*)sloc;
        bool is64 = true;
        for (int i = 1; i < NSHOTc*NSRCc*2; i += 2)
            if (w32[i] != 0u) { is64 = false; break; }
        int e = (shot*NSRCc + tid) * 2;
        int sy, sx;
        if (is64) { sy = (int)w32[2*e]; sx = (int)w32[2*(e+1)]; }
        else      { const int* w = (const int*)sloc; sy = w[e]; sx = w[e+1]; }
        float vv = v[sy*NYg + sx];
        sh_key[tid]   = ((sy + PADc) << 9) | (sx + PADc);
        sh_scale[tid] = vv * vv * (DTc*DTc);
    }
    if (tid == 0) {
        const unsigned* w32 = (const unsigned*)rloc;
        bool is64 = true;
        for (int i = 1; i < NSHOTc*NRECc*2; i += 2)
            if (w32[i] != 0u) { is64 = false; break; }
        int n = 0;
        for (int rr = 0; rr < NRECc; rr++) {
            int e = (shot*NRECc + rr) * 2;
            int ry, rx;
            if (is64) { ry = (int)w32[2*e]; rx = (int)w32[2*(e+1)]; }
            else      { const int* w = (const int*)rloc; ry = w[e]; rx = w[e+1]; }
            int yp = ry + PADc;
            if (yp >= y0 && yp < y0 + myR) {
                sh_rr2[n] = yp - y0;
                sh_rx[n]  = rx + PADc;
                sh_ro[n]  = shot*NRECc + rr;
                n++;
            }
        }
        sh_rn = n;
    }

    init_bar(cta);   // init visible everywhere; all g_arr slots == 1

    float* wbase  = g_state + shot*4*Fc;
    float* pybase = wbase + 2*Fc;
    const float* v2 = g_state + 8*Fc;
    const float* amp_s = amp + shot*NSRCc*NTc;
    const int nrec = sh_rn;

    unsigned* my_arr = &g_arr[cta*32];
    const unsigned* up_arr = has_up ? &g_arr[(cta-1)*32] : my_arr;
    const unsigned* dn_arr = has_dn ? &g_arr[(cta+1)*32] : my_arr;

    if (!big) {
        run_loop<2>(tid, y0, has_up, has_dn, wbase, pybase, v2, amp_s, out,
                    psix_s, sh_key, sh_scale, nrec, sh_rr2, sh_rx, sh_ro,
                    my_arr, up_arr, dn_arr);
    } else {
        run_loop<3>(tid, y0, has_up, has_dn, wbase, pybase, v2, amp_s, out,
                    psix_s, sh_key, sh_scale, nrec, sh_rr2, sh_rx, sh_ro,
                    my_arr, up_arr, dn_arr);
    }
}

extern "C" void kernel_launch(void* const* d_in, const int* in_sizes, int n_in,
                              void* d_out, int out_size)
{
    const float* v    = (const float*)d_in[0];
    const float* amp  = (const float*)d_in[1];
    const void*  sloc = d_in[2];
    const void*  rloc = d_in[3];
    wave_kernel<<<NCTA, TPB>>>(v, amp, sloc, rloc, (float*)d_out);
}